// round 3
// baseline (speedup 1.0000x reference)
#include <cuda_runtime.h>
#include <math.h>

#define NB   4
#define NS   4224
#define ND   1024
#define NDM  64
#define NDK  128
#define NL   528
#define NSEG 8
#define NM   16
#define EPSV 1e-5f

typedef unsigned long long u64;

__device__ __forceinline__ u64 pk2(float lo, float hi) {
    u64 r; asm("mov.b64 %0,{%1,%2};" : "=l"(r) : "f"(lo), "f"(hi)); return r;
}
__device__ __forceinline__ void fma2(u64 &d, u64 a, u64 b) {
    asm("fma.rn.f32x2 %0,%1,%2,%0;" : "+l"(d) : "l"(a), "l"(b));
}
__device__ __forceinline__ float2 up2(u64 v) {
    float2 f; asm("mov.b64 {%0,%1},%2;" : "=f"(f.x), "=f"(f.y) : "l"(v)); return f;
}

// ---------------- device scratch ----------------
__device__ __align__(16) float g_Q [NB*NS*NDK];     // dpfp features
__device__ __align__(16) float g_T [NB*NS*NDK];     // masked, den-normalized T = Q@K^T
__device__ __align__(16) float g_Kt[NB*NDK*NDK];    // K transposed: [b][dkey i][rank]
__device__ __align__(16) float g_NI[NB*NDK*ND];     // new_info rows: [b][rank][d]
__device__ __align__(16) float g_mem [NB*NM*ND];
__device__ __align__(16) float g_prev[NB*NM*ND];    // already divided by (k.z+eps)

// ---------------- K0: Q = dpfp(hs @ W_mq) ----------------
// grid 132, block 256; tile 128 rows x 64 cols, K=1024, kc=16; f32x2 row-pairs
__global__ void k0_projq(const float* __restrict__ hs, const float* __restrict__ Wmq)
{
    __shared__ float As[16*128];   // [k][row]
    __shared__ float Bs[16*64];    // [k][col]
    __shared__ float Xs[128*65];
    int tid = threadIdx.x;
    int rowBase = blockIdx.x * 128;
    int tx = tid & 15, ty = tid >> 4;
    u64 acc[4][4];                 // [rowpair p][col j]
    #pragma unroll
    for (int p = 0; p < 4; p++)
        #pragma unroll
        for (int j = 0; j < 4; j++) acc[p][j] = 0ull;

    for (int k0 = 0; k0 < ND; k0 += 16) {
        #pragma unroll
        for (int it = 0; it < 2; it++) {
            int f = it*256 + tid;
            int row = f >> 2; int q = (f & 3) * 4;
            float4 v4 = *reinterpret_cast<const float4*>(
                &hs[(size_t)(rowBase + row)*ND + k0 + q]);
            As[(q+0)*128+row] = v4.x; As[(q+1)*128+row] = v4.y;
            As[(q+2)*128+row] = v4.z; As[(q+3)*128+row] = v4.w;
        }
        {
            int kr = tid >> 4; int c = (tid & 15) * 4;
            *reinterpret_cast<float4*>(&Bs[kr*64 + c]) =
                *reinterpret_cast<const float4*>(&Wmq[(size_t)(k0+kr)*NDM + c]);
        }
        __syncthreads();
        #pragma unroll
        for (int k = 0; k < 16; k++) {
            u64 a2[4];
            #pragma unroll
            for (int p = 0; p < 4; p++)
                a2[p] = *reinterpret_cast<const u64*>(&As[k*128 + ty*8 + 2*p]);
            #pragma unroll
            for (int j = 0; j < 4; j++) {
                float bv = Bs[k*64 + tx*4 + j];
                u64 b2 = pk2(bv, bv);
                #pragma unroll
                for (int p = 0; p < 4; p++) fma2(acc[p][j], a2[p], b2);
            }
        }
        __syncthreads();
    }
    #pragma unroll
    for (int p = 0; p < 4; p++)
        #pragma unroll
        for (int j = 0; j < 4; j++) {
            float2 f = up2(acc[p][j]);
            Xs[(ty*8+2*p  )*65 + tx*4 + j] = f.x;
            Xs[(ty*8+2*p+1)*65 + tx*4 + j] = f.y;
        }
    __syncthreads();
    #pragma unroll
    for (int t = 0; t < 64; t++) {
        int idx = t*256 + tid;
        int row = idx >> 7, i = idx & 127;
        int im1 = (i + 127) & 127;
        float a = (i  < 64) ? fmaxf( Xs[row*65 + i     ], 0.f)
                            : fmaxf(-Xs[row*65 + i - 64], 0.f);
        float b = (im1 < 64) ? fmaxf( Xs[row*65 + im1     ], 0.f)
                             : fmaxf(-Xs[row*65 + im1 - 64], 0.f);
        g_Q[(size_t)(rowBase + row)*NDK + i] = a*b;
    }
}

// ---------------- kA: per mem-token: assoc -> mem -> x -> k -> prev ----------------
// grid 64 (b*16+m), 256 threads
__global__ void kA(const float* __restrict__ mo, const float* __restrict__ Wmk, int seg)
{
    __shared__ float q[NDK], kv[NDK], tt[NDK], x[NDM], xp[256], mem[ND], red[NDK];
    __shared__ float den_s, kz_s;
    int tid = threadIdx.x;
    int b = blockIdx.x >> 4, m = blockIdx.x & 15;
    int R = seg * NM;
    int row = seg*NL + (NL - NM) + m;
    size_t rbase = (size_t)b*NS + row;
    const float* Kt  = &g_Kt[(size_t)b*NDK*NDK];
    const float* NIb = &g_NI[(size_t)b*NDK*ND];

    if (tid < NDK) q[tid] = g_Q[rbase*NDK + tid];
    __syncthreads();

    if (tid < NDK) {
        float a = 0.f;
        if (tid < R) {
            #pragma unroll 4
            for (int i = 0; i < NDK; i++) a += q[i]*Kt[i*NDK + tid];
        }
        tt[tid] = a; red[tid] = a;
    }
    __syncthreads();
    for (int s2 = 64; s2 > 0; s2 >>= 1) {
        if (tid < s2) red[tid] += red[tid + s2];
        __syncthreads();
    }
    if (tid == 0) den_s = red[0] + EPSV;
    __syncthreads();

    float inv = 1.f/den_s;
    #pragma unroll
    for (int it = 0; it < 4; it++) {
        int d = it*256 + tid;
        float a = 0.f;
        #pragma unroll 4
        for (int r = 0; r < R; r++) a += tt[r]*NIb[(size_t)r*ND + d];
        float mv = a*inv + mo[rbase*ND + d];
        mem[d] = mv;
        g_mem[((size_t)b*NM + m)*ND + d] = mv;
    }
    __syncthreads();

    {   // x = mem @ W_mk
        int j = tid >> 2, part = tid & 3;
        float a = 0.f;
        #pragma unroll 4
        for (int d = part*256; d < part*256 + 256; d++) a += mem[d]*Wmk[(size_t)d*NDM + j];
        xp[tid] = a;
    }
    __syncthreads();
    if (tid < NDM) x[tid] = xp[tid*4] + xp[tid*4+1] + xp[tid*4+2] + xp[tid*4+3];
    __syncthreads();

    if (tid < NDK) {   // k = dpfp(x)
        int i = tid, im1 = (i + 127) & 127;
        float a  = (i  < 64) ? fmaxf(x[i], 0.f)      : fmaxf(-x[i-64], 0.f);
        float b2 = (im1< 64) ? fmaxf(x[im1], 0.f)    : fmaxf(-x[im1-64], 0.f);
        float kk = a*b2;
        kv[i] = kk;
        g_Kt[(size_t)b*NDK*NDK + (size_t)i*NDK + (R + m)] = kk;
    }
    __syncthreads();

    if (tid < NDK) {   // t2 = k @ K^T (old ranks only)
        float a = 0.f;
        if (tid < R) {
            #pragma unroll 4
            for (int i = 0; i < NDK; i++) a += kv[i]*Kt[i*NDK + tid];
        }
        tt[tid] = a; red[tid] = a;
    }
    __syncthreads();
    for (int s2 = 64; s2 > 0; s2 >>= 1) {
        if (tid < s2) red[tid] += red[tid + s2];
        __syncthreads();
    }
    if (tid == 0) kz_s = red[0] + EPSV;
    __syncthreads();

    float invz = 1.f/kz_s;
    #pragma unroll
    for (int it = 0; it < 4; it++) {
        int d = it*256 + tid;
        float a = 0.f;
        #pragma unroll 4
        for (int r = 0; r < R; r++) a += tt[r]*NIb[(size_t)r*ND + d];
        g_prev[((size_t)b*NM + m)*ND + d] = a*invz;
    }
}

// ---------------- kB: v/gate GEMM + ni epilogue -> NI rows ----------------
// grid 128 (b*32+ct), 256 thr; tile 16 rows x 32 cols x 2 mats, K=1024, kc=64
__global__ void kB(const float* __restrict__ Wmv, const float* __restrict__ Wmb,
                   const float* __restrict__ bmb, int seg)
{
    __shared__ float As[16*64];    // [m][k]
    __shared__ float Bv[64*32];    // [k][c]
    __shared__ float Bb[64*32];
    int tid = threadIdx.x;
    int b = blockIdx.x >> 5, ct = blockIdx.x & 31;
    int ty = tid >> 4, tx = tid & 15;   // row m, colpair
    u64 accv = 0ull, accb = 0ull;

    for (int k0 = 0; k0 < ND; k0 += 64) {
        {
            int m2 = tid >> 4; int q = (tid & 15) * 4;
            *reinterpret_cast<float4*>(&As[m2*64 + q]) =
                *reinterpret_cast<const float4*>(&g_mem[((size_t)b*NM + m2)*ND + k0 + q]);
        }
        #pragma unroll
        for (int it = 0; it < 2; it++) {
            int f = it*256 + tid;
            int kr = f >> 3; int c = (f & 7) * 4;
            *reinterpret_cast<float4*>(&Bv[kr*32 + c]) =
                *reinterpret_cast<const float4*>(&Wmv[(size_t)(k0+kr)*ND + ct*32 + c]);
            *reinterpret_cast<float4*>(&Bb[kr*32 + c]) =
                *reinterpret_cast<const float4*>(&Wmb[(size_t)(k0+kr)*ND + ct*32 + c]);
        }
        __syncthreads();
        #pragma unroll
        for (int k = 0; k < 64; k++) {
            float a = As[ty*64 + k];
            u64 a2 = pk2(a, a);
            u64 bv = *reinterpret_cast<const u64*>(&Bv[k*32 + tx*2]);
            u64 bb = *reinterpret_cast<const u64*>(&Bb[k*32 + tx*2]);
            fma2(accv, a2, bv);
            fma2(accb, a2, bb);
        }
        __syncthreads();
    }
    int c = ct*32 + tx*2;
    float2 v2 = up2(accv), g2 = up2(accb);
    float2 bias = *reinterpret_cast<const float2*>(&bmb[c]);
    size_t pix = ((size_t)b*NM + ty)*ND + c;
    float2 pv = *reinterpret_cast<const float2*>(&g_prev[pix]);
    float ga = 1.f/(1.f + expf(-(g2.x + bias.x)));
    float gb = 1.f/(1.f + expf(-(g2.y + bias.y)));
    float2 ni = make_float2(ga*(v2.x - pv.x), gb*(v2.y - pv.y));
    int rank = seg*NM + ty;
    *reinterpret_cast<float2*>(&g_NI[((size_t)b*NDK + rank)*ND + c]) = ni;
}

// ---------------- kT: T = mask(Q @ K^T)/den ----------------
// grid (66, 4), 256 thr; tile 64 rows x 128 rank-cols, K=128, kc=32
__global__ void kT()
{
    __shared__ float As[32*64];    // [k][row]
    __shared__ float Bs[32*128];   // [k][rank]
    int tid = threadIdx.x;
    int r0 = blockIdx.x * 64;
    int b  = blockIdx.y;
    int tx = tid & 15, ty = tid >> 4;
    u64 acc[4][4];                 // [row i][colpair j]
    #pragma unroll
    for (int i = 0; i < 4; i++)
        #pragma unroll
        for (int j = 0; j < 4; j++) acc[i][j] = 0ull;

    for (int k0 = 0; k0 < NDK; k0 += 32) {
        #pragma unroll
        for (int it = 0; it < 2; it++) {
            int f = it*256 + tid;
            int r = f >> 3; int q = (f & 7) * 4;
            float4 v4 = *reinterpret_cast<const float4*>(
                &g_Q[((size_t)b*NS + r0 + r)*NDK + k0 + q]);
            As[(q+0)*64+r] = v4.x; As[(q+1)*64+r] = v4.y;
            As[(q+2)*64+r] = v4.z; As[(q+3)*64+r] = v4.w;
        }
        #pragma unroll
        for (int it = 0; it < 4; it++) {
            int f = it*256 + tid;
            int kr = f >> 5; int c = (f & 31) * 4;
            *reinterpret_cast<float4*>(&Bs[kr*128 + c]) =
                *reinterpret_cast<const float4*>(&g_Kt[(size_t)b*NDK*NDK + (size_t)(k0+kr)*NDK + c]);
        }
        __syncthreads();
        #pragma unroll
        for (int k = 0; k < 32; k++) {
            u64 a2[4], bv[4];
            #pragma unroll
            for (int i = 0; i < 4; i++) {
                float a = As[k*64 + ty*4 + i];
                a2[i] = pk2(a, a);
            }
            #pragma unroll
            for (int j = 0; j < 4; j++)
                bv[j] = *reinterpret_cast<const u64*>(&Bs[k*128 + tx*8 + 2*j]);
            #pragma unroll
            for (int i = 0; i < 4; i++)
                #pragma unroll
                for (int j = 0; j < 4; j++) fma2(acc[i][j], a2[i], bv[j]);
        }
        __syncthreads();
    }
    #pragma unroll
    for (int i = 0; i < 4; i++) {
        int row = r0 + ty*4 + i;
        int maskR = (row / NL) * NM;
        float2 tv[4];
        float rsum = 0.f;
        #pragma unroll
        for (int j = 0; j < 4; j++) {
            float2 f = up2(acc[i][j]);
            int c0 = tx*8 + 2*j;
            if (c0     >= maskR) f.x = 0.f;
            if (c0 + 1 >= maskR) f.y = 0.f;
            rsum += f.x + f.y;
            tv[j] = f;
        }
        #pragma unroll
        for (int off = 1; off < 16; off <<= 1)
            rsum += __shfl_xor_sync(0xffffffffu, rsum, off);
        float inv = 1.f/(rsum + EPSV);
        #pragma unroll
        for (int j = 0; j < 4; j++) {
            float2 o = make_float2(tv[j].x*inv, tv[j].y*inv);
            *reinterpret_cast<float2*>(&g_T[((size_t)b*NS + row)*NDK + tx*8 + 2*j]) = o;
        }
    }
}

// ---------------- k4: out = mo + tanh(T @ NI) ----------------
// grid (8, 66, 4), 256 thr; tile 64 rows x 128 cols, K=128, kc=32
__global__ void k4_out(const float* __restrict__ mo, float* __restrict__ out)
{
    __shared__ float As[32*64];    // [k][row]
    __shared__ float Bs[32*128];   // [k][col]
    int tid = threadIdx.x;
    int c0 = blockIdx.x * 128;
    int r0 = blockIdx.y * 64;
    int b  = blockIdx.z;
    int tx = tid & 15, ty = tid >> 4;
    u64 acc[4][4];
    #pragma unroll
    for (int i = 0; i < 4; i++)
        #pragma unroll
        for (int j = 0; j < 4; j++) acc[i][j] = 0ull;

    for (int k0 = 0; k0 < NDK; k0 += 32) {
        #pragma unroll
        for (int it = 0; it < 2; it++) {
            int f = it*256 + tid;
            int r = f >> 3; int q = (f & 7) * 4;
            float4 v4 = *reinterpret_cast<const float4*>(
                &g_T[((size_t)b*NS + r0 + r)*NDK + k0 + q]);
            As[(q+0)*64+r] = v4.x; As[(q+1)*64+r] = v4.y;
            As[(q+2)*64+r] = v4.z; As[(q+3)*64+r] = v4.w;
        }
        #pragma unroll
        for (int it = 0; it < 4; it++) {
            int f = it*256 + tid;
            int kr = f >> 5; int c = (f & 31) * 4;
            *reinterpret_cast<float4*>(&Bs[kr*128 + c]) =
                *reinterpret_cast<const float4*>(&g_NI[(size_t)b*NDK*ND + (size_t)(k0+kr)*ND + c0 + c]);
        }
        __syncthreads();
        #pragma unroll
        for (int k = 0; k < 32; k++) {
            u64 a2[4], bv[4];
            #pragma unroll
            for (int i = 0; i < 4; i++) {
                float a = As[k*64 + ty*4 + i];
                a2[i] = pk2(a, a);
            }
            #pragma unroll
            for (int j = 0; j < 4; j++)
                bv[j] = *reinterpret_cast<const u64*>(&Bs[k*128 + tx*8 + 2*j]);
            #pragma unroll
            for (int i = 0; i < 4; i++)
                #pragma unroll
                for (int j = 0; j < 4; j++) fma2(acc[i][j], a2[i], bv[j]);
        }
        __syncthreads();
    }
    #pragma unroll
    for (int i = 0; i < 4; i++) {
        int row = r0 + ty*4 + i;
        size_t ob = ((size_t)b*NS + row)*ND + c0 + tx*8;
        #pragma unroll
        for (int j = 0; j < 4; j++) {
            float2 f = up2(acc[i][j]);
            float2 mv = *reinterpret_cast<const float2*>(&mo[ob + 2*j]);
            float2 o = make_float2(mv.x + tanhf(f.x), mv.y + tanhf(f.y));
            *reinterpret_cast<float2*>(&out[ob + 2*j]) = o;
        }
    }
}

// ---------------- launch ----------------
extern "C" void kernel_launch(void* const* d_in, const int* in_sizes, int n_in,
                              void* d_out, int out_size)
{
    const float* hs  = (const float*)d_in[0];
    const float* mo  = (const float*)d_in[1];
    const float* Wmq = (const float*)d_in[2];
    const float* Wmk = (const float*)d_in[3];
    const float* Wmv = (const float*)d_in[4];
    const float* Wmb = (const float*)d_in[5];
    const float* bmb = (const float*)d_in[6];
    float* out = (float*)d_out;

    k0_projq<<<132, 256>>>(hs, Wmq);
    for (int seg = 0; seg < NSEG; seg++) {
        kA<<<64, 256>>>(mo, Wmk, seg);
        kB<<<128, 256>>>(Wmv, Wmb, bmb, seg);
    }
    kT<<<dim3(66, 4), 256>>>();
    k4_out<<<dim3(8, 66, 4), 256>>>(mo, out);
}

// round 4
// speedup vs baseline: 1.1928x; 1.1928x over previous
#include <cuda_runtime.h>
#include <math.h>

#define NB   4
#define NS   4224
#define ND   1024
#define NDM  64
#define NDK  128
#define NL   528
#define NSEG 8
#define NM   16
#define EPSV 1e-5f

typedef unsigned long long u64;

__device__ __forceinline__ u64 pk2(float lo, float hi) {
    u64 r; asm("mov.b64 %0,{%1,%2};" : "=l"(r) : "f"(lo), "f"(hi)); return r;
}
__device__ __forceinline__ void fma2(u64 &d, u64 a, u64 b) {
    asm("fma.rn.f32x2 %0,%1,%2,%0;" : "+l"(d) : "l"(a), "l"(b));
}
__device__ __forceinline__ float2 up2(u64 v) {
    float2 f; asm("mov.b64 {%0,%1},%2;" : "=f"(f.x), "=f"(f.y) : "l"(v)); return f;
}
__device__ __forceinline__ float tanh_hw(float x) {
    float r; asm("tanh.approx.f32 %0,%1;" : "=f"(r) : "f"(x)); return r;
}

// ---------------- device scratch ----------------
__device__ __align__(16) float g_Q [NB*NS*NDK];     // dpfp features
__device__ __align__(16) float g_T [NB*NS*NDK];     // masked, normalized T = Q@K^T
__device__ __align__(16) float g_Kt[NB*NDK*NDK];    // K transposed: [b][feat i][rank]
__device__ __align__(16) float g_NI[NB*NDK*ND];     // new_info rows: [b][rank][d]
__device__ __align__(16) float g_mem[NB*NM*ND];
__device__ __align__(16) float g_xp [NB*16*NM*NDM]; // x partials per coltile
__device__ __align__(16) float g_t2 [NB*NM*NDK];    // k @ K^T (masked)
__device__ __align__(16) float g_kz [NB*NM];        // k.z + eps

// ---------------- K0: Q = dpfp(hs @ W_mq) ----------------
__global__ void k0_projq(const float* __restrict__ hs, const float* __restrict__ Wmq)
{
    __shared__ float As[16*128];
    __shared__ float Bs[16*64];
    __shared__ float Xs[128*65];
    int tid = threadIdx.x;
    int rowBase = blockIdx.x * 128;
    int tx = tid & 15, ty = tid >> 4;
    u64 acc[4][4];
    #pragma unroll
    for (int p = 0; p < 4; p++)
        #pragma unroll
        for (int j = 0; j < 4; j++) acc[p][j] = 0ull;

    for (int k0 = 0; k0 < ND; k0 += 16) {
        #pragma unroll
        for (int it = 0; it < 2; it++) {
            int f = it*256 + tid;
            int row = f >> 2; int q = (f & 3) * 4;
            float4 v4 = *reinterpret_cast<const float4*>(
                &hs[(size_t)(rowBase + row)*ND + k0 + q]);
            As[(q+0)*128+row] = v4.x; As[(q+1)*128+row] = v4.y;
            As[(q+2)*128+row] = v4.z; As[(q+3)*128+row] = v4.w;
        }
        {
            int kr = tid >> 4; int c = (tid & 15) * 4;
            *reinterpret_cast<float4*>(&Bs[kr*64 + c]) =
                *reinterpret_cast<const float4*>(&Wmq[(size_t)(k0+kr)*NDM + c]);
        }
        __syncthreads();
        #pragma unroll
        for (int k = 0; k < 16; k++) {
            u64 a2[4];
            #pragma unroll
            for (int p = 0; p < 4; p++)
                a2[p] = *reinterpret_cast<const u64*>(&As[k*128 + ty*8 + 2*p]);
            #pragma unroll
            for (int j = 0; j < 4; j++) {
                float bv = Bs[k*64 + tx*4 + j];
                u64 b2 = pk2(bv, bv);
                #pragma unroll
                for (int p = 0; p < 4; p++) fma2(acc[p][j], a2[p], b2);
            }
        }
        __syncthreads();
    }
    #pragma unroll
    for (int p = 0; p < 4; p++)
        #pragma unroll
        for (int j = 0; j < 4; j++) {
            float2 f = up2(acc[p][j]);
            Xs[(ty*8+2*p  )*65 + tx*4 + j] = f.x;
            Xs[(ty*8+2*p+1)*65 + tx*4 + j] = f.y;
        }
    __syncthreads();
    #pragma unroll
    for (int t = 0; t < 64; t++) {
        int idx = t*256 + tid;
        int row = idx >> 7, i = idx & 127;
        int im1 = (i + 127) & 127;
        float a = (i  < 64) ? fmaxf( Xs[row*65 + i     ], 0.f)
                            : fmaxf(-Xs[row*65 + i - 64], 0.f);
        float b = (im1 < 64) ? fmaxf( Xs[row*65 + im1     ], 0.f)
                             : fmaxf(-Xs[row*65 + im1 - 64], 0.f);
        g_Q[(size_t)(rowBase + row)*NDK + i] = a*b;
    }
}

// ---------------- kS2: tt, den, assoc -> mem; + x partial ----------------
// grid 64 (b*16+ct), 256 thr; coltile 64
__global__ void kS2(const float* __restrict__ mo, const float* __restrict__ Wmk, int seg)
{
    __shared__ float q[16*128];
    __shared__ float ph[2*16*128];
    __shared__ float ttm[16*128];
    __shared__ float Ns[16*64];
    __shared__ float Ms[16*64];
    __shared__ float den[16];
    __shared__ float red[128];
    int tid = threadIdx.x;
    int b = blockIdx.x >> 4, ct = blockIdx.x & 15, cb = ct*64;
    int R = seg * NM;
    size_t rbase = (size_t)b*NS + seg*NL + (NL - NM);
    const float* Kt  = &g_Kt[(size_t)b*NDK*NDK];
    const float* NIb = &g_NI[(size_t)b*NDK*ND];

    #pragma unroll
    for (int f = tid; f < 512; f += 256) {
        int m = f >> 5; int qo = (f & 31) * 4;
        *reinterpret_cast<float4*>(&q[m*128 + qo]) =
            *reinterpret_cast<const float4*>(&g_Q[(rbase + m)*NDK + qo]);
    }
    __syncthreads();
    {   // tt partials: thread = (r, half of i)
        int r = tid & 127, h = tid >> 7;
        float a[16];
        #pragma unroll
        for (int m = 0; m < 16; m++) a[m] = 0.f;
        #pragma unroll 4
        for (int i = h*64; i < h*64 + 64; i++) {
            float kt = Kt[i*128 + r];
            #pragma unroll
            for (int m = 0; m < 16; m++) a[m] += q[m*128 + i]*kt;
        }
        #pragma unroll
        for (int m = 0; m < 16; m++) ph[(h*16 + m)*128 + r] = a[m];
    }
    __syncthreads();
    if (tid < 128) {
        int r = tid;
        #pragma unroll
        for (int m = 0; m < 16; m++) {
            float v = ph[m*128 + r] + ph[(16 + m)*128 + r];
            ttm[m*128 + r] = (r < R) ? v : 0.f;
        }
    }
    __syncthreads();
    if (tid < 128) {
        int m = tid >> 3, p = tid & 7;
        float s = 0.f;
        #pragma unroll
        for (int r = p*16; r < p*16 + 16; r++) s += ttm[m*128 + r];
        red[tid] = s;
    }
    __syncthreads();
    if (tid < 16) {
        float s = 0.f;
        #pragma unroll
        for (int j = 0; j < 8; j++) s += red[tid*8 + j];
        den[tid] = s + EPSV;
    }
    __syncthreads();
    // assoc over rank chunks of 16
    int mg = tid >> 6, d = tid & 63;
    float acc[4] = {0.f, 0.f, 0.f, 0.f};
    for (int r0 = 0; r0 < R; r0 += 16) {
        {
            int rr = tid >> 4; int cc = (tid & 15) * 4;
            *reinterpret_cast<float4*>(&Ns[rr*64 + cc]) =
                *reinterpret_cast<const float4*>(&NIb[(size_t)(r0+rr)*ND + cb + cc]);
        }
        __syncthreads();
        #pragma unroll
        for (int rr = 0; rr < 16; rr++) {
            float nv = Ns[rr*64 + d];
            #pragma unroll
            for (int i = 0; i < 4; i++) acc[i] += ttm[(mg*4+i)*128 + r0 + rr]*nv;
        }
        __syncthreads();
    }
    #pragma unroll
    for (int i = 0; i < 4; i++) {
        int m = mg*4 + i;
        float mv = acc[i]/den[m] + mo[(rbase + m)*ND + cb + d];
        g_mem[((size_t)b*NM + m)*ND + cb + d] = mv;
        Ms[m*64 + d] = mv;
    }
    __syncthreads();
    // x partial for this 64-d slab: xp[m][j] = sum_dd Ms[m][dd]*Wmk[cb+dd][j]
    {
        int j = tid & 63, mq = tid >> 6;
        float a2[4] = {0.f, 0.f, 0.f, 0.f};
        #pragma unroll 4
        for (int dd = 0; dd < 64; dd++) {
            float w = Wmk[(size_t)(cb + dd)*NDM + j];
            #pragma unroll
            for (int i = 0; i < 4; i++) a2[i] += Ms[(mq*4+i)*64 + dd]*w;
        }
        #pragma unroll
        for (int i = 0; i < 4; i++)
            g_xp[(((size_t)b*16 + ct)*NM + mq*4 + i)*NDM + j] = a2[i];
    }
}

// ---------------- kS3: x-reduce, dpfp->k (Kt col), t2 = k@K^T, kz ----------------
// grid 4, 256 thr
__global__ void kS3(int seg)
{
    __shared__ float xsm[NM*NDM];
    __shared__ float kvs[NM*NDK];
    __shared__ float ph[2*NM*NDK];
    __shared__ float red[128];
    int tid = threadIdx.x;
    int b = blockIdx.x;
    int R = seg * NM;

    {   // sum 16 coltile partials
        int f0 = tid*4;
        float4 s = make_float4(0.f, 0.f, 0.f, 0.f);
        #pragma unroll
        for (int p = 0; p < 16; p++) {
            float4 v = *reinterpret_cast<const float4*>(
                &g_xp[((size_t)b*16 + p)*NM*NDM + f0]);
            s.x += v.x; s.y += v.y; s.z += v.z; s.w += v.w;
        }
        *reinterpret_cast<float4*>(&xsm[f0]) = s;
    }
    __syncthreads();
    #pragma unroll
    for (int it = 0; it < 8; it++) {   // dpfp 16x128
        int f = it*256 + tid;
        int m = f >> 7, i = f & 127;
        int im1 = (i + 127) & 127;
        float a  = (i  < 64) ? fmaxf( xsm[m*64 + i     ], 0.f)
                             : fmaxf(-xsm[m*64 + i - 64], 0.f);
        float b2 = (im1< 64) ? fmaxf( xsm[m*64 + im1     ], 0.f)
                             : fmaxf(-xsm[m*64 + im1 - 64], 0.f);
        float kk = a*b2;
        kvs[m*128 + i] = kk;
        g_Kt[(size_t)b*NDK*NDK + (size_t)i*NDK + (R + m)] = kk;
    }
    __syncthreads();
    {   // t2 partials
        int r = tid & 127, h = tid >> 7;
        const float* Kt = &g_Kt[(size_t)b*NDK*NDK];
        float a[16];
        #pragma unroll
        for (int m = 0; m < 16; m++) a[m] = 0.f;
        #pragma unroll 4
        for (int i = h*64; i < h*64 + 64; i++) {
            float kt = Kt[i*128 + r];
            #pragma unroll
            for (int m = 0; m < 16; m++) a[m] += kvs[m*128 + i]*kt;
        }
        #pragma unroll
        for (int m = 0; m < 16; m++) ph[(h*16 + m)*128 + r] = a[m];
    }
    __syncthreads();
    if (tid < 128) {
        int r = tid;
        #pragma unroll
        for (int m = 0; m < 16; m++) {
            float v = ph[m*128 + r] + ph[(16 + m)*128 + r];
            v = (r < R) ? v : 0.f;
            g_t2[((size_t)b*NM + m)*NDK + r] = v;
            kvs[m*128 + r] = v;               // reuse for kz reduce
        }
    }
    __syncthreads();
    if (tid < 128) {
        int m = tid >> 3, p = tid & 7;
        float s = 0.f;
        #pragma unroll
        for (int r = p*16; r < p*16 + 16; r++) s += kvs[m*128 + r];
        red[tid] = s;
    }
    __syncthreads();
    if (tid < 16) {
        float s = 0.f;
        #pragma unroll
        for (int j = 0; j < 8; j++) s += red[tid*8 + j];
        g_kz[b*NM + tid] = s + EPSV;
    }
}

// ---------------- kB: v/gate GEMM + prev + ni epilogue -> NI rows ----------------
// grid 128 (b*32+ct), 256 thr; tile 16 rows x 32 cols, K=1024
__global__ void kB(const float* __restrict__ Wmv, const float* __restrict__ Wmb,
                   const float* __restrict__ bmb, int seg)
{
    __shared__ float As[16*64];
    __shared__ float Bv[64*32];
    __shared__ float Bb[64*32];
    __shared__ float t2s[NM*NDK];
    __shared__ float Ns[16*32];
    __shared__ float kzs[NM];
    int tid = threadIdx.x;
    int b = blockIdx.x >> 5, ct = blockIdx.x & 31;
    int R = seg * NM;
    int ty = tid >> 4, tx = tid & 15;

    #pragma unroll
    for (int f = tid; f < 512; f += 256) {
        int m = f >> 5; int qo = (f & 31) * 4;
        *reinterpret_cast<float4*>(&t2s[m*128 + qo]) =
            *reinterpret_cast<const float4*>(&g_t2[((size_t)b*NM + m)*NDK + qo]);
    }
    if (tid < NM) kzs[tid] = g_kz[b*NM + tid];
    __syncthreads();

    // prev for this block's 32 cols
    u64 accp = 0ull;
    for (int r0 = 0; r0 < R; r0 += 16) {
        if (tid < 128) {
            int rr = tid >> 3; int cc = (tid & 7) * 4;
            *reinterpret_cast<float4*>(&Ns[rr*32 + cc]) =
                *reinterpret_cast<const float4*>(
                    &g_NI[(size_t)b*NDK*ND + (size_t)(r0+rr)*ND + ct*32 + cc]);
        }
        __syncthreads();
        #pragma unroll
        for (int rr = 0; rr < 16; rr++) {
            float t = t2s[ty*128 + r0 + rr];
            fma2(accp, pk2(t, t), *reinterpret_cast<const u64*>(&Ns[rr*32 + tx*2]));
        }
        __syncthreads();
    }
    float invkz = 1.f/kzs[ty];
    float2 pvr = up2(accp);
    float2 pv = make_float2(pvr.x*invkz, pvr.y*invkz);

    // v / gate GEMM
    u64 accv = 0ull, accb = 0ull;
    for (int k0 = 0; k0 < ND; k0 += 64) {
        {
            int m2 = tid >> 4; int q = (tid & 15) * 4;
            *reinterpret_cast<float4*>(&As[m2*64 + q]) =
                *reinterpret_cast<const float4*>(&g_mem[((size_t)b*NM + m2)*ND + k0 + q]);
        }
        #pragma unroll
        for (int it = 0; it < 2; it++) {
            int f = it*256 + tid;
            int kr = f >> 3; int c = (f & 7) * 4;
            *reinterpret_cast<float4*>(&Bv[kr*32 + c]) =
                *reinterpret_cast<const float4*>(&Wmv[(size_t)(k0+kr)*ND + ct*32 + c]);
            *reinterpret_cast<float4*>(&Bb[kr*32 + c]) =
                *reinterpret_cast<const float4*>(&Wmb[(size_t)(k0+kr)*ND + ct*32 + c]);
        }
        __syncthreads();
        #pragma unroll
        for (int k = 0; k < 64; k++) {
            float a = As[ty*64 + k];
            u64 a2 = pk2(a, a);
            fma2(accv, a2, *reinterpret_cast<const u64*>(&Bv[k*32 + tx*2]));
            fma2(accb, a2, *reinterpret_cast<const u64*>(&Bb[k*32 + tx*2]));
        }
        __syncthreads();
    }
    int c = ct*32 + tx*2;
    float2 v2 = up2(accv), g2 = up2(accb);
    float2 bias = *reinterpret_cast<const float2*>(&bmb[c]);
    float ga = 1.f/(1.f + expf(-(g2.x + bias.x)));
    float gb = 1.f/(1.f + expf(-(g2.y + bias.y)));
    float2 ni = make_float2(ga*(v2.x - pv.x), gb*(v2.y - pv.y));
    int rank = R + ty;
    *reinterpret_cast<float2*>(&g_NI[((size_t)b*NDK + rank)*ND + c]) = ni;
}

// ---------------- kT: T = mask(Q @ K^T)/den ----------------
__global__ void kT()
{
    __shared__ float As[32*64];
    __shared__ float Bs[32*128];
    int tid = threadIdx.x;
    int r0 = blockIdx.x * 64;
    int b  = blockIdx.y;
    int tx = tid & 15, ty = tid >> 4;
    u64 acc[4][4];
    #pragma unroll
    for (int i = 0; i < 4; i++)
        #pragma unroll
        for (int j = 0; j < 4; j++) acc[i][j] = 0ull;

    for (int k0 = 0; k0 < NDK; k0 += 32) {
        #pragma unroll
        for (int it = 0; it < 2; it++) {
            int f = it*256 + tid;
            int r = f >> 3; int q = (f & 7) * 4;
            float4 v4 = *reinterpret_cast<const float4*>(
                &g_Q[((size_t)b*NS + r0 + r)*NDK + k0 + q]);
            As[(q+0)*64+r] = v4.x; As[(q+1)*64+r] = v4.y;
            As[(q+2)*64+r] = v4.z; As[(q+3)*64+r] = v4.w;
        }
        #pragma unroll
        for (int it = 0; it < 4; it++) {
            int f = it*256 + tid;
            int kr = f >> 5; int c = (f & 31) * 4;
            *reinterpret_cast<float4*>(&Bs[kr*128 + c]) =
                *reinterpret_cast<const float4*>(&g_Kt[(size_t)b*NDK*NDK + (size_t)(k0+kr)*NDK + c]);
        }
        __syncthreads();
        #pragma unroll
        for (int k = 0; k < 32; k++) {
            u64 a2[4], bv[4];
            #pragma unroll
            for (int i = 0; i < 4; i++) {
                float a = As[k*64 + ty*4 + i];
                a2[i] = pk2(a, a);
            }
            #pragma unroll
            for (int j = 0; j < 4; j++)
                bv[j] = *reinterpret_cast<const u64*>(&Bs[k*128 + tx*8 + 2*j]);
            #pragma unroll
            for (int i = 0; i < 4; i++)
                #pragma unroll
                for (int j = 0; j < 4; j++) fma2(acc[i][j], a2[i], bv[j]);
        }
        __syncthreads();
    }
    #pragma unroll
    for (int i = 0; i < 4; i++) {
        int row = r0 + ty*4 + i;
        int maskR = (row / NL) * NM;
        float2 tv[4];
        float rsum = 0.f;
        #pragma unroll
        for (int j = 0; j < 4; j++) {
            float2 f = up2(acc[i][j]);
            int c0 = tx*8 + 2*j;
            if (c0     >= maskR) f.x = 0.f;
            if (c0 + 1 >= maskR) f.y = 0.f;
            rsum += f.x + f.y;
            tv[j] = f;
        }
        #pragma unroll
        for (int off = 1; off < 16; off <<= 1)
            rsum += __shfl_xor_sync(0xffffffffu, rsum, off);
        float inv = 1.f/(rsum + EPSV);
        #pragma unroll
        for (int j = 0; j < 4; j++) {
            float2 o = make_float2(tv[j].x*inv, tv[j].y*inv);
            *reinterpret_cast<float2*>(&g_T[((size_t)b*NS + row)*NDK + tx*8 + 2*j]) = o;
        }
    }
}

// ---------------- k4: out = mo + tanh(T @ NI) ----------------
__global__ void k4_out(const float* __restrict__ mo, float* __restrict__ out)
{
    __shared__ float As[32*64];
    __shared__ float Bs[32*128];
    int tid = threadIdx.x;
    int c0 = blockIdx.x * 128;
    int r0 = blockIdx.y * 64;
    int b  = blockIdx.z;
    int tx = tid & 15, ty = tid >> 4;
    u64 acc[4][4];
    #pragma unroll
    for (int i = 0; i < 4; i++)
        #pragma unroll
        for (int j = 0; j < 4; j++) acc[i][j] = 0ull;

    for (int k0 = 0; k0 < NDK; k0 += 32) {
        #pragma unroll
        for (int it = 0; it < 2; it++) {
            int f = it*256 + tid;
            int r = f >> 3; int q = (f & 7) * 4;
            float4 v4 = *reinterpret_cast<const float4*>(
                &g_T[((size_t)b*NS + r0 + r)*NDK + k0 + q]);
            As[(q+0)*64+r] = v4.x; As[(q+1)*64+r] = v4.y;
            As[(q+2)*64+r] = v4.z; As[(q+3)*64+r] = v4.w;
        }
        #pragma unroll
        for (int it = 0; it < 4; it++) {
            int f = it*256 + tid;
            int kr = f >> 5; int c = (f & 31) * 4;
            *reinterpret_cast<float4*>(&Bs[kr*128 + c]) =
                *reinterpret_cast<const float4*>(&g_NI[(size_t)b*NDK*ND + (size_t)(k0+kr)*ND + c0 + c]);
        }
        __syncthreads();
        #pragma unroll
        for (int k = 0; k < 32; k++) {
            u64 a2[4], bv[4];
            #pragma unroll
            for (int i = 0; i < 4; i++) {
                float a = As[k*64 + ty*4 + i];
                a2[i] = pk2(a, a);
            }
            #pragma unroll
            for (int j = 0; j < 4; j++)
                bv[j] = *reinterpret_cast<const u64*>(&Bs[k*128 + tx*8 + 2*j]);
            #pragma unroll
            for (int i = 0; i < 4; i++)
                #pragma unroll
                for (int j = 0; j < 4; j++) fma2(acc[i][j], a2[i], bv[j]);
        }
        __syncthreads();
    }
    #pragma unroll
    for (int i = 0; i < 4; i++) {
        int row = r0 + ty*4 + i;
        size_t ob = ((size_t)b*NS + row)*ND + c0 + tx*8;
        #pragma unroll
        for (int j = 0; j < 4; j++) {
            float2 f = up2(acc[i][j]);
            float2 mv = *reinterpret_cast<const float2*>(&mo[ob + 2*j]);
            float2 o = make_float2(mv.x + tanh_hw(f.x), mv.y + tanh_hw(f.y));
            *reinterpret_cast<float2*>(&out[ob + 2*j]) = o;
        }
    }
}

// ---------------- launch ----------------
extern "C" void kernel_launch(void* const* d_in, const int* in_sizes, int n_in,
                              void* d_out, int out_size)
{
    const float* hs  = (const float*)d_in[0];
    const float* mo  = (const float*)d_in[1];
    const float* Wmq = (const float*)d_in[2];
    const float* Wmk = (const float*)d_in[3];
    const float* Wmv = (const float*)d_in[4];
    const float* Wmb = (const float*)d_in[5];
    const float* bmb = (const float*)d_in[6];
    float* out = (float*)d_out;

    k0_projq<<<132, 256>>>(hs, Wmq);
    for (int seg = 0; seg < NSEG; seg++) {
        kS2<<<64, 256>>>(mo, Wmk, seg);
        kS3<<<4, 256>>>(seg);
        kB<<<128, 256>>>(Wmv, Wmb, bmb, seg);
    }
    kT<<<dim3(66, 4), 256>>>();
    k4_out<<<dim3(8, 66, 4), 256>>>(mo, out);
}